// round 1
// baseline (speedup 1.0000x reference)
#include <cuda_runtime.h>
#include <math.h>

// ---------------- problem constants (fixed by reference) ----------------
#define NN 50000
#define EE 600000
#define HH 128
#define GG 256
#define EPSF 1e-5f
#define SLOPE 0.2f

// ---------------- scratch (__device__ globals; no allocs allowed) -------
__device__ __align__(16) float g_tmp[NN * HH];   // GEMM output (pre-aggregation h)
__device__ __align__(16) float g_acc[NN * HH];   // scatter accumulator
__device__ __align__(16) float g_h  [NN * HH];   // post BN+ReLU activations
__device__ float g_dis[NN];                      // rsqrt(deg)
__device__ float g_als[NN], g_ald[NN];           // GAT per-node attention logits
__device__ float g_m  [NN], g_den[NN];           // GAT softmax max / denom
__device__ float g_e  [EE];                      // GAT per-edge e / ex
__device__ double g_sum[HH], g_sq[HH];           // BN stats (double for accuracy)
__device__ float g_scale[HH], g_shift[HH];       // BN affine, precomputed
__device__ __align__(16) float g_pooled[GG * HH];
__device__ float g_cnt[GG];
__device__ __align__(16) float g_z[GG * HH];

// ---------------- helpers ------------------------------------------------
__device__ __forceinline__ float lrelu(float x) { return x > 0.f ? x : SLOPE * x; }

__device__ __forceinline__ void red_add_f4(float* p, float4 v) {
    asm volatile("red.global.add.v4.f32 [%0], {%1,%2,%3,%4};"
                 :: "l"(__cvta_generic_to_global(p)),
                    "f"(v.x), "f"(v.y), "f"(v.z), "f"(v.w)
                 : "memory");
}

__device__ __forceinline__ void atomicMaxF(float* addr, float value) {
    if (value >= 0.f)
        atomicMax((int*)addr, __float_as_int(value));
    else
        atomicMin((unsigned int*)addr, __float_as_uint(value));
}

// ---------------- degree / norm ------------------------------------------
__global__ void k_deg_init() {
    int i = blockIdx.x * blockDim.x + threadIdx.x;
    if (i < NN) g_dis[i] = 1.0f;   // self loop
}
__global__ void k_deg_count(const int* __restrict__ dst) {
    int e = blockIdx.x * blockDim.x + threadIdx.x;
    if (e < EE) atomicAdd(&g_dis[dst[e]], 1.0f);
}
__global__ void k_deg_finish() {
    int i = blockIdx.x * blockDim.x + threadIdx.x;
    if (i < NN) g_dis[i] = rsqrtf(g_dis[i]);
}

// ---------------- GEMM: C(g_tmp)[n,128] = A[n,128] @ W[128,128] ----------
// If Aext == nullptr, A = g_h (device-global activations).
__global__ void k_gemm128(const float* __restrict__ Aext,
                          const float* __restrict__ W) {
    const float* A = Aext ? Aext : g_h;
    __shared__ float As[64][17];
    __shared__ float Ws[16][128];
    int t = threadIdx.x;                 // 256 threads
    int row0 = blockIdx.x * 64;
    int tx = t & 15, ty = t >> 4;        // tx: 16 col-groups of 8, ty: 16 row-groups of 4
    float acc[4][8];
#pragma unroll
    for (int i = 0; i < 4; i++)
#pragma unroll
        for (int j = 0; j < 8; j++) acc[i][j] = 0.f;

    for (int kt = 0; kt < 128; kt += 16) {
        {   // load A tile 64x16 (1024 elems / 256 thr = 4 = float4)
            int idx = t * 4;
            int r = idx >> 4, kk = idx & 15;
            int grow = row0 + r;
            float4 v = make_float4(0.f, 0.f, 0.f, 0.f);
            if (grow < NN) v = *(const float4*)&A[grow * 128 + kt + kk];
            As[r][kk] = v.x; As[r][kk + 1] = v.y; As[r][kk + 2] = v.z; As[r][kk + 3] = v.w;
        }
        {   // load W tile 16x128 (2048 elems / 256 thr = 8 floats)
            int idx = t * 8;
            int r = idx >> 7, c = idx & 127;
            *(float4*)&Ws[r][c]     = *(const float4*)&W[(kt + r) * 128 + c];
            *(float4*)&Ws[r][c + 4] = *(const float4*)&W[(kt + r) * 128 + c + 4];
        }
        __syncthreads();
#pragma unroll
        for (int kk = 0; kk < 16; kk++) {
            float a[4];
#pragma unroll
            for (int i = 0; i < 4; i++) a[i] = As[ty * 4 + i][kk];
            float4 w0 = *(float4*)&Ws[kk][tx * 8];
            float4 w1 = *(float4*)&Ws[kk][tx * 8 + 4];
            float w[8] = {w0.x, w0.y, w0.z, w0.w, w1.x, w1.y, w1.z, w1.w};
#pragma unroll
            for (int i = 0; i < 4; i++)
#pragma unroll
                for (int j = 0; j < 8; j++) acc[i][j] = fmaf(a[i], w[j], acc[i][j]);
        }
        __syncthreads();
    }
#pragma unroll
    for (int i = 0; i < 4; i++) {
        int grow = row0 + ty * 4 + i;
        if (grow < NN) {
            float4 o0 = make_float4(acc[i][0], acc[i][1], acc[i][2], acc[i][3]);
            float4 o1 = make_float4(acc[i][4], acc[i][5], acc[i][6], acc[i][7]);
            *(float4*)&g_tmp[grow * 128 + tx * 8]     = o0;
            *(float4*)&g_tmp[grow * 128 + tx * 8 + 4] = o1;
        }
    }
}

// ---------------- GCN aggregation -----------------------------------------
__global__ void k_gcn_init(const float* __restrict__ bias) {
    int idx = blockIdx.x * blockDim.x + threadIdx.x;
    if (idx >= NN * HH) return;
    int i = idx >> 7, f = idx & 127;
    float d = g_dis[i];
    g_acc[idx] = g_tmp[idx] * d * d + bias[f];
}
__global__ void k_gcn_scatter(const int* __restrict__ src, const int* __restrict__ dst) {
    int w = (blockIdx.x * blockDim.x + threadIdx.x) >> 5;
    if (w >= EE) return;
    int l = threadIdx.x & 31;
    int s = src[w], d = dst[w];
    float nrm = g_dis[s] * g_dis[d];
    float4 v = ((const float4*)&g_tmp[s * HH])[l];
    v.x *= nrm; v.y *= nrm; v.z *= nrm; v.w *= nrm;
    red_add_f4(&g_acc[d * HH + l * 4], v);
}

// ---------------- BatchNorm + ReLU ----------------------------------------
__global__ void k_stats_zero() {
    int c = threadIdx.x;
    if (c < HH) { g_sum[c] = 0.0; g_sq[c] = 0.0; }
}
__global__ void k_stats() {
    int c = threadIdx.x;                 // 128 threads = columns
    float s = 0.f, sq = 0.f;
    for (int r = blockIdx.x; r < NN; r += gridDim.x) {
        float v = g_acc[r * HH + c];
        s += v; sq += v * v;
    }
    atomicAdd(&g_sum[c], (double)s);
    atomicAdd(&g_sq[c], (double)sq);
}
__global__ void k_bn_prep(const float* __restrict__ gamma, const float* __restrict__ beta) {
    int c = threadIdx.x;
    if (c >= HH) return;
    double mu = g_sum[c] / (double)NN;
    double var = g_sq[c] / (double)NN - mu * mu;
    float vf = (float)var; if (vf < 0.f) vf = 0.f;
    float sc = gamma[c] * rsqrtf(vf + EPSF);
    g_scale[c] = sc;
    g_shift[c] = beta[c] - (float)mu * sc;
}
__global__ void k_bn_relu() {
    int idx = blockIdx.x * blockDim.x + threadIdx.x;
    if (idx >= NN * HH) return;
    int f = idx & 127;
    g_h[idx] = fmaxf(fmaf(g_acc[idx], g_scale[f], g_shift[f]), 0.f);
}

// ---------------- GAT -------------------------------------------------------
__global__ void k_att(const float* __restrict__ as, const float* __restrict__ ad) {
    int w = (blockIdx.x * blockDim.x + threadIdx.x) >> 5;
    if (w >= NN) return;
    int l = threadIdx.x & 31;
    float4 hv = ((const float4*)&g_tmp[w * HH])[l];
    float4 a = ((const float4*)as)[l];
    float4 b = ((const float4*)ad)[l];
    float s = hv.x * a.x + hv.y * a.y + hv.z * a.z + hv.w * a.w;
    float d = hv.x * b.x + hv.y * b.y + hv.z * b.z + hv.w * b.w;
#pragma unroll
    for (int o = 16; o; o >>= 1) {
        s += __shfl_xor_sync(0xffffffffu, s, o);
        d += __shfl_xor_sync(0xffffffffu, d, o);
    }
    if (!l) { g_als[w] = s; g_ald[w] = d; }
}
__global__ void k_gat_minit() {
    int i = blockIdx.x * blockDim.x + threadIdx.x;
    if (i < NN) g_m[i] = lrelu(g_als[i] + g_ald[i]);   // self-loop e
}
__global__ void k_gat_emax(const int* __restrict__ src, const int* __restrict__ dst) {
    int e = blockIdx.x * blockDim.x + threadIdx.x;
    if (e >= EE) return;
    float v = lrelu(g_als[src[e]] + g_ald[dst[e]]);
    g_e[e] = v;
    atomicMaxF(&g_m[dst[e]], v);
}
__global__ void k_gat_deninit() {
    int i = blockIdx.x * blockDim.x + threadIdx.x;
    if (i < NN) g_den[i] = expf(lrelu(g_als[i] + g_ald[i]) - g_m[i]);  // self-loop ex
}
__global__ void k_gat_exsum(const int* __restrict__ dst) {
    int e = blockIdx.x * blockDim.x + threadIdx.x;
    if (e >= EE) return;
    float ex = expf(g_e[e] - g_m[dst[e]]);
    g_e[e] = ex;
    atomicAdd(&g_den[dst[e]], ex);
}
__global__ void k_gat_alpha_self() {   // overwrite g_als with self-loop alpha
    int i = blockIdx.x * blockDim.x + threadIdx.x;
    if (i < NN) g_als[i] = expf(lrelu(g_als[i] + g_ald[i]) - g_m[i]) / g_den[i];
}
__global__ void k_gat_init(const float* __restrict__ bias) {
    int idx = blockIdx.x * blockDim.x + threadIdx.x;
    if (idx >= NN * HH) return;
    int i = idx >> 7, f = idx & 127;
    g_acc[idx] = g_tmp[idx] * g_als[i] + bias[f];
}
__global__ void k_gat_scatter(const int* __restrict__ src, const int* __restrict__ dst) {
    int w = (blockIdx.x * blockDim.x + threadIdx.x) >> 5;
    if (w >= EE) return;
    int l = threadIdx.x & 31;
    int s = src[w], d = dst[w];
    float alpha = g_e[w] / g_den[d];
    float4 v = ((const float4*)&g_tmp[s * HH])[l];
    v.x *= alpha; v.y *= alpha; v.z *= alpha; v.w *= alpha;
    red_add_f4(&g_acc[d * HH + l * 4], v);
}

// ---------------- pooling + MLP -------------------------------------------
__global__ void k_pool_zero() {
    int idx = blockIdx.x * blockDim.x + threadIdx.x;
    if (idx < GG * HH) g_pooled[idx] = 0.f;
    if (idx < GG) g_cnt[idx] = 0.f;
}
__global__ void k_pool_scatter(const int* __restrict__ batch) {
    int w = (blockIdx.x * blockDim.x + threadIdx.x) >> 5;
    if (w >= NN) return;
    int l = threadIdx.x & 31;
    int b = batch[w];
    if (!l) atomicAdd(&g_cnt[b], 1.0f);
    float4 v = ((const float4*)&g_h[w * HH])[l];
    red_add_f4(&g_pooled[b * HH + l * 4], v);
}
__global__ void k_pool_div() {
    int idx = blockIdx.x * blockDim.x + threadIdx.x;
    if (idx >= GG * HH) return;
    g_pooled[idx] /= fmaxf(g_cnt[idx >> 7], 1.0f);
}
__global__ void k_mlp1(const float* __restrict__ fw1, const float* __restrict__ fb1) {
    __shared__ float p[HH];
    int g = blockIdx.x, t = threadIdx.x;
    p[t] = g_pooled[g * HH + t];
    __syncthreads();
    float s = fb1[t];
#pragma unroll 8
    for (int k = 0; k < HH; k++) s = fmaf(p[k], fw1[k * HH + t], s);
    g_z[g * HH + t] = fmaxf(s, 0.f);
}
__global__ void k_mlp2(const float* __restrict__ fw2, const float* __restrict__ fb2,
                       float* __restrict__ out) {
    int w = (blockIdx.x * blockDim.x + threadIdx.x) >> 5;
    if (w >= GG) return;
    int l = threadIdx.x & 31;
    float4 z = ((const float4*)&g_z[w * HH])[l];
    float4 ww = ((const float4*)fw2)[l];
    float s = z.x * ww.x + z.y * ww.y + z.z * ww.z + z.w * ww.w;
#pragma unroll
    for (int o = 16; o; o >>= 1) s += __shfl_xor_sync(0xffffffffu, s, o);
    if (!l) out[w] = s + fb2[0];
}

// ---------------- launch ----------------------------------------------------
extern "C" void kernel_launch(void* const* d_in, const int* in_sizes, int n_in,
                              void* d_out, int out_size) {
    const float* x       = (const float*)d_in[0];
    const int*   ei      = (const int*)d_in[1];
    const int*   batch   = (const int*)d_in[2];
    const float* W1      = (const float*)d_in[3];
    const float* b1      = (const float*)d_in[4];
    const float* g1      = (const float*)d_in[5];
    const float* be1     = (const float*)d_in[6];
    const float* Wg      = (const float*)d_in[7];
    const float* att_src = (const float*)d_in[8];
    const float* att_dst = (const float*)d_in[9];
    const float* bg      = (const float*)d_in[10];
    const float* g2      = (const float*)d_in[11];
    const float* be2     = (const float*)d_in[12];
    const float* W3      = (const float*)d_in[13];
    const float* b3      = (const float*)d_in[14];
    const float* g3      = (const float*)d_in[15];
    const float* be3     = (const float*)d_in[16];
    const float* fw1     = (const float*)d_in[17];
    const float* fb1     = (const float*)d_in[18];
    const float* fw2     = (const float*)d_in[19];
    const float* fb2     = (const float*)d_in[20];
    float* out = (float*)d_out;

    const int* src = ei;
    const int* dst = ei + EE;

    const int NB   = (NN + 255) / 256;          // node-scalar blocks
    const int EB   = (EE + 255) / 256;          // edge-scalar blocks
    const int NHB  = (NN * HH + 255) / 256;     // node*feat blocks
    const int EWB  = (EE * 32 + 255) / 256;     // warp-per-edge blocks
    const int NWB  = (NN * 32 + 255) / 256;     // warp-per-node blocks
    const int GEMB = (NN + 63) / 64;            // gemm blocks

    // degrees / symmetric norm (shared by both GCN layers)
    k_deg_init<<<NB, 256>>>();
    k_deg_count<<<EB, 256>>>(dst);
    k_deg_finish<<<NB, 256>>>();

    // ---- layer 1: GCN ----
    k_gemm128<<<GEMB, 256>>>(x, W1);
    k_gcn_init<<<NHB, 256>>>(b1);
    k_gcn_scatter<<<EWB, 256>>>(src, dst);
    k_stats_zero<<<1, 128>>>();
    k_stats<<<256, 128>>>();
    k_bn_prep<<<1, 128>>>(g1, be1);
    k_bn_relu<<<NHB, 256>>>();

    // ---- layer 2: GAT ----
    k_gemm128<<<GEMB, 256>>>(nullptr, Wg);      // A = g_h
    k_att<<<NWB, 256>>>(att_src, att_dst);
    k_gat_minit<<<NB, 256>>>();
    k_gat_emax<<<EB, 256>>>(src, dst);
    k_gat_deninit<<<NB, 256>>>();
    k_gat_exsum<<<EB, 256>>>(dst);
    k_gat_alpha_self<<<NB, 256>>>();
    k_gat_init<<<NHB, 256>>>(bg);
    k_gat_scatter<<<EWB, 256>>>(src, dst);
    k_stats_zero<<<1, 128>>>();
    k_stats<<<256, 128>>>();
    k_bn_prep<<<1, 128>>>(g2, be2);
    k_bn_relu<<<NHB, 256>>>();

    // ---- layer 3: GCN ----
    k_gemm128<<<GEMB, 256>>>(nullptr, W3);      // A = g_h
    k_gcn_init<<<NHB, 256>>>(b3);
    k_gcn_scatter<<<EWB, 256>>>(src, dst);
    k_stats_zero<<<1, 128>>>();
    k_stats<<<256, 128>>>();
    k_bn_prep<<<1, 128>>>(g3, be3);
    k_bn_relu<<<NHB, 256>>>();

    // ---- pool + MLP ----
    k_pool_zero<<<(GG * HH + 255) / 256, 256>>>();
    k_pool_scatter<<<NWB, 256>>>(batch);
    k_pool_div<<<(GG * HH + 255) / 256, 256>>>();
    k_mlp1<<<GG, 128>>>(fw1, fb1);
    k_mlp2<<<(GG * 32 + 255) / 256, 256>>>(fw2, fb2, out);
}

// round 2
// speedup vs baseline: 1.5748x; 1.5748x over previous
#include <cuda_runtime.h>
#include <math.h>

// ---------------- problem constants ----------------
#define NN 50000
#define EE 600000
#define HH 128
#define GG 256
#define EPSF 1e-5f
#define SLOPE 0.2f
#define NCH 196            // ceil(NN/256)

// ---------------- scratch ----------------
__device__ __align__(16) float g_tmp[NN * HH];   // GEMM output (pre-aggregation)
__device__ __align__(16) float g_acc[NN * HH];   // aggregated (pre-BN) activations
__device__ float g_dis[NN];                      // rsqrt(1+deg)
__device__ float g_als[NN], g_ald[NN];           // GAT attention logits
__device__ int   g_deg[NN];
__device__ int   g_start[NN + 1];
__device__ int   g_fill[NN];
__device__ int   g_esrc[EE];                     // src sorted by dst (CSR)
__device__ int   g_part[NCH], g_poff[NCH];
__device__ float g_partS[256 * HH], g_partQ[256 * HH];
__device__ __align__(16) float g_scale[HH], g_shift[HH];
__device__ __align__(16) float g_pooled[GG * HH];
__device__ float g_cnt[GG];
__device__ __align__(16) float g_z[GG * HH];

__device__ __forceinline__ float lrelu(float x) { return x > 0.f ? x : SLOPE * x; }

__device__ __forceinline__ void red_add_f4(float* p, float4 v) {
    asm volatile("red.global.add.v4.f32 [%0], {%1,%2,%3,%4};"
                 :: "l"(__cvta_generic_to_global(p)),
                    "f"(v.x), "f"(v.y), "f"(v.z), "f"(v.w)
                 : "memory");
}

// ---------------- zero + CSR build ----------------
__global__ void k_zero() {
    int i = blockIdx.x * blockDim.x + threadIdx.x;
    if (i < NN) g_deg[i] = 0;
    if (i < GG) g_cnt[i] = 0.f;
    if (i < GG * HH) g_pooled[i] = 0.f;
}
__global__ void k_hist(const int* __restrict__ dst) {
    int e = blockIdx.x * blockDim.x + threadIdx.x;
    if (e < EE) atomicAdd(&g_deg[dst[e]], 1);
}
__global__ void k_scan1() {
    __shared__ int sm[256];
    int i = blockIdx.x * 256 + threadIdx.x;
    int v = (i < NN) ? g_deg[i] : 0;
    sm[threadIdx.x] = v; __syncthreads();
    for (int o = 128; o; o >>= 1) {
        if (threadIdx.x < o) sm[threadIdx.x] += sm[threadIdx.x + o];
        __syncthreads();
    }
    if (!threadIdx.x) g_part[blockIdx.x] = sm[0];
}
__global__ void k_scan2() {
    __shared__ int sm[256];
    int t = threadIdx.x;
    int v = (t < NCH) ? g_part[t] : 0;
    sm[t] = v; __syncthreads();
    for (int o = 1; o < 256; o <<= 1) {
        int x = (t >= o) ? sm[t - o] : 0;
        __syncthreads();
        sm[t] += x; __syncthreads();
    }
    if (t < NCH) g_poff[t] = sm[t] - v;
}
__global__ void k_scan3() {
    __shared__ int sm[256];
    int t = threadIdx.x, i = blockIdx.x * 256 + t;
    int v = (i < NN) ? g_deg[i] : 0;
    sm[t] = v; __syncthreads();
    for (int o = 1; o < 256; o <<= 1) {
        int x = (t >= o) ? sm[t - o] : 0;
        __syncthreads();
        sm[t] += x; __syncthreads();
    }
    if (i < NN) {
        int excl = sm[t] - v + g_poff[blockIdx.x];
        g_start[i] = excl;
        g_fill[i] = 0;
        g_dis[i] = rsqrtf(1.0f + (float)v);
        if (i == NN - 1) g_start[NN] = excl + v;
    }
}
__global__ void k_fill(const int* __restrict__ src, const int* __restrict__ dst) {
    int e = blockIdx.x * blockDim.x + threadIdx.x;
    if (e >= EE) return;
    int d = dst[e];
    int pos = g_start[d] + atomicAdd(&g_fill[d], 1);
    g_esrc[pos] = src[e];
}

// ---------------- GEMM: g_tmp[n,128] = A[n,128] @ W[128,128] ----------------
// BN=true: A = g_acc with y = relu(a*scale + shift) applied on load.
template<bool BN>
__global__ __launch_bounds__(256, 2)
void k_gemm(const float* __restrict__ Aext, const float* __restrict__ W) {
    __shared__ float As[2][8][132];
    __shared__ float Ws[2][8][128];
    __shared__ float s_sc[128], s_sh[128];
    const float* A = BN ? (const float*)g_acc : Aext;
    int t = threadIdx.x;
    if (BN) {
        if (t < 128) { s_sc[t] = g_scale[t]; s_sh[t] = g_shift[t]; }
        __syncthreads();
    }
    int row0 = blockIdx.x * 128;
    int lr = t >> 1, lc = (t & 1) * 4;      // A tile load: row, k-offset
    int wr = t >> 5, wc = (t & 31) * 4;     // W tile load
    int tx = t & 15, ty = t >> 4;

    float acc[8][8];
#pragma unroll
    for (int i = 0; i < 8; i++)
#pragma unroll
        for (int j = 0; j < 8; j++) acc[i][j] = 0.f;

    auto loadA = [&](int st, int kt) {
        int grow = row0 + lr;
        float4 v = make_float4(0.f, 0.f, 0.f, 0.f);
        if (grow < NN) v = *(const float4*)&A[grow * 128 + kt + lc];
        if (BN) {
            int k0 = kt + lc;
            v.x = fmaxf(fmaf(v.x, s_sc[k0 + 0], s_sh[k0 + 0]), 0.f);
            v.y = fmaxf(fmaf(v.y, s_sc[k0 + 1], s_sh[k0 + 1]), 0.f);
            v.z = fmaxf(fmaf(v.z, s_sc[k0 + 2], s_sh[k0 + 2]), 0.f);
            v.w = fmaxf(fmaf(v.w, s_sc[k0 + 3], s_sh[k0 + 3]), 0.f);
        }
        As[st][lc + 0][lr] = v.x; As[st][lc + 1][lr] = v.y;
        As[st][lc + 2][lr] = v.z; As[st][lc + 3][lr] = v.w;
    };
    auto loadW = [&](int st, int kt) {
        *(float4*)&Ws[st][wr][wc] = *(const float4*)&W[(kt + wr) * 128 + wc];
    };

    loadA(0, 0); loadW(0, 0);
    __syncthreads();
    for (int kt = 0; kt < 128; kt += 8) {
        int cur = (kt >> 3) & 1, nxt = cur ^ 1;
        if (kt + 8 < 128) { loadA(nxt, kt + 8); loadW(nxt, kt + 8); }
#pragma unroll
        for (int kk = 0; kk < 8; kk++) {
            float a[8], w[8];
            *(float4*)&a[0] = *(const float4*)&As[cur][kk][ty * 8];
            *(float4*)&a[4] = *(const float4*)&As[cur][kk][ty * 8 + 4];
            *(float4*)&w[0] = *(const float4*)&Ws[cur][kk][tx * 8];
            *(float4*)&w[4] = *(const float4*)&Ws[cur][kk][tx * 8 + 4];
#pragma unroll
            for (int i = 0; i < 8; i++)
#pragma unroll
                for (int j = 0; j < 8; j++)
                    acc[i][j] = fmaf(a[i], w[j], acc[i][j]);
        }
        __syncthreads();
    }
#pragma unroll
    for (int i = 0; i < 8; i++) {
        int grow = row0 + ty * 8 + i;
        if (grow < NN) {
            *(float4*)&g_tmp[grow * 128 + tx * 8]     = *(float4*)&acc[i][0];
            *(float4*)&g_tmp[grow * 128 + tx * 8 + 4] = *(float4*)&acc[i][4];
        }
    }
}

// ---------------- GCN segment aggregation (self loop + bias fused) ----------
__global__ void k_gcn_seg(const int* __restrict__ dummy, const float* __restrict__ bias) {
    int d = (blockIdx.x * blockDim.x + threadIdx.x) >> 5;
    if (d >= NN) return;
    int l = threadIdx.x & 31;
    float dd = g_dis[d];
    float4 b4 = ((const float4*)bias)[l];
    float4 self = ((const float4*)&g_tmp[d * HH])[l];
    float dd2 = dd * dd;
    float4 acc = make_float4(fmaf(self.x, dd2, b4.x), fmaf(self.y, dd2, b4.y),
                             fmaf(self.z, dd2, b4.z), fmaf(self.w, dd2, b4.w));
    int s0 = g_start[d], s1 = g_start[d + 1];
#pragma unroll 4
    for (int j = s0; j < s1; j++) {
        int s = g_esrc[j];
        float nrm = g_dis[s] * dd;
        float4 v = ((const float4*)&g_tmp[s * HH])[l];
        acc.x = fmaf(v.x, nrm, acc.x); acc.y = fmaf(v.y, nrm, acc.y);
        acc.z = fmaf(v.z, nrm, acc.z); acc.w = fmaf(v.w, nrm, acc.w);
    }
    ((float4*)&g_acc[d * HH])[l] = acc;
}

// ---------------- GAT -------------------------------------------------------
__global__ void k_att(const float* __restrict__ as, const float* __restrict__ ad) {
    int w = (blockIdx.x * blockDim.x + threadIdx.x) >> 5;
    if (w >= NN) return;
    int l = threadIdx.x & 31;
    float4 hv = ((const float4*)&g_tmp[w * HH])[l];
    float4 a = ((const float4*)as)[l];
    float4 b = ((const float4*)ad)[l];
    float s = hv.x * a.x + hv.y * a.y + hv.z * a.z + hv.w * a.w;
    float d = hv.x * b.x + hv.y * b.y + hv.z * b.z + hv.w * b.w;
#pragma unroll
    for (int o = 16; o; o >>= 1) {
        s += __shfl_xor_sync(0xffffffffu, s, o);
        d += __shfl_xor_sync(0xffffffffu, d, o);
    }
    if (!l) { g_als[w] = s; g_ald[w] = d; }
}

// full GAT edge softmax + aggregation, one kernel, warp per dst
__global__ void k_gat_seg(const float* __restrict__ bias) {
    int d = (blockIdx.x * blockDim.x + threadIdx.x) >> 5;
    if (d >= NN) return;
    int l = threadIdx.x & 31;
    float ald_d = g_ald[d];
    float self_e = lrelu(g_als[d] + ald_d);
    int s0 = g_start[d], s1 = g_start[d + 1];
    // phase 1: segment max
    float m = self_e;
    for (int j = s0 + l; j < s1; j += 32)
        m = fmaxf(m, lrelu(g_als[g_esrc[j]] + ald_d));
#pragma unroll
    for (int o = 16; o; o >>= 1) m = fmaxf(m, __shfl_xor_sync(0xffffffffu, m, o));
    // phase 2: denom
    float den = 0.f;
    for (int j = s0 + l; j < s1; j += 32)
        den += expf(lrelu(g_als[g_esrc[j]] + ald_d) - m);
#pragma unroll
    for (int o = 16; o; o >>= 1) den += __shfl_xor_sync(0xffffffffu, den, o);
    den += expf(self_e - m);
    float rden = 1.0f / den;
    // phase 3: aggregate
    float4 b4 = ((const float4*)bias)[l];
    float a_self = expf(self_e - m) * rden;
    float4 self = ((const float4*)&g_tmp[d * HH])[l];
    float4 acc = make_float4(fmaf(self.x, a_self, b4.x), fmaf(self.y, a_self, b4.y),
                             fmaf(self.z, a_self, b4.z), fmaf(self.w, a_self, b4.w));
#pragma unroll 2
    for (int j = s0; j < s1; j++) {
        int s = g_esrc[j];
        float al = expf(lrelu(g_als[s] + ald_d) - m) * rden;
        float4 v = ((const float4*)&g_tmp[s * HH])[l];
        acc.x = fmaf(v.x, al, acc.x); acc.y = fmaf(v.y, al, acc.y);
        acc.z = fmaf(v.z, al, acc.z); acc.w = fmaf(v.w, al, acc.w);
    }
    ((float4*)&g_acc[d * HH])[l] = acc;
}

// ---------------- BatchNorm stats ----------------
__global__ void k_stats() {           // grid 256, block 128
    int c = threadIdx.x;
    float s = 0.f, sq = 0.f;
    for (int r = blockIdx.x; r < NN; r += 256) {
        float v = g_acc[r * HH + c];
        s += v; sq += v * v;
    }
    g_partS[blockIdx.x * HH + c] = s;
    g_partQ[blockIdx.x * HH + c] = sq;
}
__global__ void k_bn_prep(const float* __restrict__ gamma, const float* __restrict__ beta) {
    int c = threadIdx.x;               // 128 threads
    double S = 0.0, Q = 0.0;
    for (int b = 0; b < 256; b++) { S += g_partS[b * HH + c]; Q += g_partQ[b * HH + c]; }
    double mu = S / (double)NN;
    double var = Q / (double)NN - mu * mu;
    float vf = (float)var; if (vf < 0.f) vf = 0.f;
    float sc = gamma[c] * rsqrtf(vf + EPSF);
    g_scale[c] = sc;
    g_shift[c] = beta[c] - (float)mu * sc;
}

// ---------------- pooling (BN3 + ReLU applied on the fly) + MLP ----------------
__global__ void k_pool_scatter(const int* __restrict__ batch) {
    int w = (blockIdx.x * blockDim.x + threadIdx.x) >> 5;
    if (w >= NN) return;
    int l = threadIdx.x & 31;
    int b = batch[w];
    if (!l) atomicAdd(&g_cnt[b], 1.0f);
    float4 v = ((const float4*)&g_acc[w * HH])[l];
    float4 sc = ((const float4*)g_scale)[l];
    float4 sh = ((const float4*)g_shift)[l];
    v.x = fmaxf(fmaf(v.x, sc.x, sh.x), 0.f);
    v.y = fmaxf(fmaf(v.y, sc.y, sh.y), 0.f);
    v.z = fmaxf(fmaf(v.z, sc.z, sh.z), 0.f);
    v.w = fmaxf(fmaf(v.w, sc.w, sh.w), 0.f);
    red_add_f4(&g_pooled[b * HH + l * 4], v);
}
__global__ void k_mlp1(const float* __restrict__ fw1, const float* __restrict__ fb1) {
    __shared__ float p[HH];
    int g = blockIdx.x, t = threadIdx.x;
    float inv = 1.0f / fmaxf(g_cnt[g], 1.0f);
    p[t] = g_pooled[g * HH + t] * inv;
    __syncthreads();
    float s = fb1[t];
#pragma unroll 8
    for (int k = 0; k < HH; k++) s = fmaf(p[k], fw1[k * HH + t], s);
    g_z[g * HH + t] = fmaxf(s, 0.f);
}
__global__ void k_mlp2(const float* __restrict__ fw2, const float* __restrict__ fb2,
                       float* __restrict__ out) {
    int w = (blockIdx.x * blockDim.x + threadIdx.x) >> 5;
    if (w >= GG) return;
    int l = threadIdx.x & 31;
    float4 z = ((const float4*)&g_z[w * HH])[l];
    float4 ww = ((const float4*)fw2)[l];
    float s = z.x * ww.x + z.y * ww.y + z.z * ww.z + z.w * ww.w;
#pragma unroll
    for (int o = 16; o; o >>= 1) s += __shfl_xor_sync(0xffffffffu, s, o);
    if (!l) out[w] = s + fb2[0];
}

// ---------------- launch ----------------
extern "C" void kernel_launch(void* const* d_in, const int* in_sizes, int n_in,
                              void* d_out, int out_size) {
    const float* x       = (const float*)d_in[0];
    const int*   ei      = (const int*)d_in[1];
    const int*   batch   = (const int*)d_in[2];
    const float* W1      = (const float*)d_in[3];
    const float* b1      = (const float*)d_in[4];
    const float* g1      = (const float*)d_in[5];
    const float* be1     = (const float*)d_in[6];
    const float* Wg      = (const float*)d_in[7];
    const float* att_src = (const float*)d_in[8];
    const float* att_dst = (const float*)d_in[9];
    const float* bg      = (const float*)d_in[10];
    const float* g2      = (const float*)d_in[11];
    const float* be2     = (const float*)d_in[12];
    const float* W3      = (const float*)d_in[13];
    const float* b3      = (const float*)d_in[14];
    const float* g3      = (const float*)d_in[15];
    const float* be3     = (const float*)d_in[16];
    const float* fw1     = (const float*)d_in[17];
    const float* fb1     = (const float*)d_in[18];
    const float* fw2     = (const float*)d_in[19];
    const float* fb2     = (const float*)d_in[20];
    float* out = (float*)d_out;

    const int* src = ei;
    const int* dst = ei + EE;

    const int NB  = (NN + 255) / 256;
    const int EB  = (EE + 255) / 256;
    const int NWB = (NN * 32 + 255) / 256;
    const int GEMB = (NN + 127) / 128;

    // CSR build (shared by all layers)
    k_zero<<<NB, 256>>>();
    k_hist<<<EB, 256>>>(dst);
    k_scan1<<<NCH, 256>>>();
    k_scan2<<<1, 256>>>();
    k_scan3<<<NCH, 256>>>();
    k_fill<<<EB, 256>>>(src, dst);

    // ---- layer 1: GCN ----
    k_gemm<false><<<GEMB, 256>>>(x, W1);
    k_gcn_seg<<<NWB, 256>>>(nullptr, b1);
    k_stats<<<256, 128>>>();
    k_bn_prep<<<1, 128>>>(g1, be1);

    // ---- layer 2: GAT (BN1+ReLU fused into GEMM A-load) ----
    k_gemm<true><<<GEMB, 256>>>(nullptr, Wg);
    k_att<<<NWB, 256>>>(att_src, att_dst);
    k_gat_seg<<<NWB, 256>>>(bg);
    k_stats<<<256, 128>>>();
    k_bn_prep<<<1, 128>>>(g2, be2);

    // ---- layer 3: GCN (BN2+ReLU fused into GEMM A-load) ----
    k_gemm<true><<<GEMB, 256>>>(nullptr, W3);
    k_gcn_seg<<<NWB, 256>>>(nullptr, b3);
    k_stats<<<256, 128>>>();
    k_bn_prep<<<1, 128>>>(g3, be3);

    // ---- pool (BN3+ReLU fused) + MLP ----
    k_pool_scatter<<<NWB, 256>>>(batch);
    k_mlp1<<<GG, 128>>>(fw1, fb1);
    k_mlp2<<<(GG * 32 + 255) / 256, 256>>>(fw2, fb2, out);
}

// round 3
// speedup vs baseline: 2.8245x; 1.7936x over previous
#include <cuda_runtime.h>
#include <math.h>
#include <stdint.h>

// ---------------- problem constants ----------------
#define NN 50000
#define EE 600000
#define HH 128
#define GG 256
#define EPSF 1e-5f
#define SLOPE 0.2f
#define NCH 196            // ceil(NN/256)
#define NSTRIPE 64

// ---------------- scratch ----------------
__device__ __align__(16) float g_tmp[NN * HH];   // GEMM output
__device__ __align__(16) float g_acc[NN * HH];   // aggregated pre-BN activations
__device__ float g_dis[NN];
__device__ float g_als[NN], g_ald[NN];
__device__ int   g_deg[NN];
__device__ int   g_start[NN + 1];
__device__ int   g_fill[NN];
__device__ int   g_esrc[EE];
__device__ unsigned int g_bstate[NCH];           // decoupled-lookback state
__device__ float g_pS[NSTRIPE * HH], g_pQ[NSTRIPE * HH];
__device__ __align__(16) float g_scale[HH], g_shift[HH];
__device__ __align__(16) float g_pooled[GG * HH];
__device__ float g_cnt[GG];
__device__ __align__(16) float g_z[GG * HH];

__device__ __forceinline__ float lrelu(float x) { return x > 0.f ? x : SLOPE * x; }

__device__ __forceinline__ float to_tf32(float x) {
    float r;
    asm("cvt.rna.tf32.f32 %0, %1;" : "=f"(r) : "f"(x));
    return r;
}

__device__ __forceinline__ void red_add_f4(float* p, float4 v) {
    asm volatile("red.global.add.v4.f32 [%0], {%1,%2,%3,%4};"
                 :: "l"(__cvta_generic_to_global(p)),
                    "f"(v.x), "f"(v.y), "f"(v.z), "f"(v.w)
                 : "memory");
}

// ---------------- zero + CSR build ----------------
__global__ void k_zero() {
    int i = blockIdx.x * blockDim.x + threadIdx.x;
    if (i < NN) g_deg[i] = 0;
    if (i < NCH) g_bstate[i] = 0u;
    if (i < GG) g_cnt[i] = 0.f;
    if (i < GG * HH) g_pooled[i] = 0.f;
    if (i < NSTRIPE * HH) { g_pS[i] = 0.f; g_pQ[i] = 0.f; }
}
__global__ void k_hist(const int* __restrict__ dst) {
    int e = blockIdx.x * blockDim.x + threadIdx.x;
    if (e < EE) atomicAdd(&g_deg[dst[e]], 1);
}
// single-kernel exclusive scan (decoupled lookback; all 196 blocks co-resident)
__global__ void k_scan() {
    __shared__ int sm[256];
    __shared__ int s_base;
    int bid = blockIdx.x, t = threadIdx.x;
    int i = bid * 256 + t;
    int v = (i < NN) ? g_deg[i] : 0;
    sm[t] = v; __syncthreads();
    for (int o = 1; o < 256; o <<= 1) {
        int x = (t >= o) ? sm[t - o] : 0;
        __syncthreads();
        sm[t] += x; __syncthreads();
    }
    int total = sm[255];
    if (t == 0) {
        if (bid == 0) {
            __threadfence();
            *(volatile unsigned int*)&g_bstate[0] = (2u << 30) | (unsigned int)total;
            s_base = 0;
        } else {
            *(volatile unsigned int*)&g_bstate[bid] = (1u << 30) | (unsigned int)total;
            __threadfence();
            int run = 0;
            for (int j = bid - 1; j >= 0; j--) {
                unsigned int st;
                do { st = *(volatile unsigned int*)&g_bstate[j]; } while ((st >> 30) == 0u);
                run += (int)(st & 0x3FFFFFFFu);
                if ((st >> 30) == 2u) break;
            }
            __threadfence();
            *(volatile unsigned int*)&g_bstate[bid] = (2u << 30) | (unsigned int)(run + total);
            s_base = run;
        }
    }
    __syncthreads();
    int base = s_base;
    if (i < NN) {
        int excl = base + sm[t] - v;
        g_start[i] = excl;
        g_fill[i] = 0;
        g_dis[i] = rsqrtf(1.0f + (float)v);
        if (i == NN - 1) g_start[NN] = excl + v;
    }
}
__global__ void k_fill(const int* __restrict__ src, const int* __restrict__ dst) {
    int e = blockIdx.x * blockDim.x + threadIdx.x;
    if (e >= EE) return;
    int d = dst[e];
    int pos = g_start[d] + atomicAdd(&g_fill[d], 1);
    g_esrc[pos] = src[e];
}

// ---------------- TF32 tensor-core GEMM ----------------
// g_tmp[n,128] = A[n,128] @ W[128,128].
// BN: A = relu(g_acc*scale + shift) applied on load.
// ATT: epilogue accumulates att_src/att_dst dots into g_als/g_ald (must be pre-zeroed).
template<bool BN, bool ATT>
__global__ __launch_bounds__(256, 2)
void k_gemm(const float* __restrict__ Aext, const float* __restrict__ W,
            const float* __restrict__ av_s, const float* __restrict__ av_d) {
    __shared__ float As[128][36];      // [row][k], pad 36 -> conflict-free frags
    __shared__ float Bs[32][136];      // [k][n],  pad 136 -> conflict-free frags
    __shared__ float s_sc[128], s_sh[128];
    __shared__ float s_as[128], s_ad[128];
    const float* A = BN ? (const float*)g_acc : Aext;
    int t = threadIdx.x;
    if (t < 128) {
        if (BN)  { s_sc[t] = g_scale[t]; s_sh[t] = g_shift[t]; }
        if (ATT) { s_as[t] = av_s[t];    s_ad[t] = av_d[t]; }
    }

    int row0 = blockIdx.x * 128;
    int warpId = t >> 5, lane = t & 31;
    int wm = warpId >> 1, wn = warpId & 1;   // 4 x 2 warp grid
    int gp = lane >> 2, qi = lane & 3;

    float acc[2][8][4];
#pragma unroll
    for (int mt = 0; mt < 2; mt++)
#pragma unroll
        for (int nt = 0; nt < 8; nt++)
#pragma unroll
            for (int j = 0; j < 4; j++) acc[mt][nt][j] = 0.f;

    int arow = t >> 3;            // A staging: 32 rows/pass, 4 passes
    int ac4  = (t & 7) * 4;
    int brow = t >> 5;            // W staging: 8 rows/pass, 4 passes
    int bc4  = (t & 31) * 4;

    for (int kt = 0; kt < 128; kt += 32) {
        __syncthreads();
        // stage A chunk 128x32 (tf32, optional BN+ReLU)
#pragma unroll
        for (int p = 0; p < 4; p++) {
            int r = p * 32 + arow;
            int grow = row0 + r;
            float4 v = make_float4(0.f, 0.f, 0.f, 0.f);
            if (grow < NN) v = *(const float4*)&A[grow * 128 + kt + ac4];
            if (BN) {
                int k0 = kt + ac4;
                v.x = fmaxf(fmaf(v.x, s_sc[k0 + 0], s_sh[k0 + 0]), 0.f);
                v.y = fmaxf(fmaf(v.y, s_sc[k0 + 1], s_sh[k0 + 1]), 0.f);
                v.z = fmaxf(fmaf(v.z, s_sc[k0 + 2], s_sh[k0 + 2]), 0.f);
                v.w = fmaxf(fmaf(v.w, s_sc[k0 + 3], s_sh[k0 + 3]), 0.f);
            }
            v.x = to_tf32(v.x); v.y = to_tf32(v.y);
            v.z = to_tf32(v.z); v.w = to_tf32(v.w);
            *(float4*)&As[r][ac4] = v;
        }
        // stage W chunk 32x128 (tf32)
#pragma unroll
        for (int p = 0; p < 4; p++) {
            int r = p * 8 + brow;
            float4 v = *(const float4*)&W[(kt + r) * 128 + bc4];
            v.x = to_tf32(v.x); v.y = to_tf32(v.y);
            v.z = to_tf32(v.z); v.w = to_tf32(v.w);
            *(float4*)&Bs[r][bc4] = v;
        }
        __syncthreads();
#pragma unroll
        for (int k8 = 0; k8 < 32; k8 += 8) {
            uint32_t a[2][4], b[8][2];
#pragma unroll
            for (int mt = 0; mt < 2; mt++) {
                int rb = wm * 32 + mt * 16 + gp;
                a[mt][0] = __float_as_uint(As[rb][k8 + qi]);
                a[mt][1] = __float_as_uint(As[rb + 8][k8 + qi]);
                a[mt][2] = __float_as_uint(As[rb][k8 + qi + 4]);
                a[mt][3] = __float_as_uint(As[rb + 8][k8 + qi + 4]);
            }
#pragma unroll
            for (int nt = 0; nt < 8; nt++) {
                int cb = wn * 64 + nt * 8 + gp;
                b[nt][0] = __float_as_uint(Bs[k8 + qi][cb]);
                b[nt][1] = __float_as_uint(Bs[k8 + qi + 4][cb]);
            }
#pragma unroll
            for (int mt = 0; mt < 2; mt++)
#pragma unroll
                for (int nt = 0; nt < 8; nt++) {
                    asm volatile(
                        "mma.sync.aligned.m16n8k8.row.col.f32.tf32.tf32.f32 "
                        "{%0,%1,%2,%3},{%4,%5,%6,%7},{%8,%9},{%0,%1,%2,%3};"
                        : "+f"(acc[mt][nt][0]), "+f"(acc[mt][nt][1]),
                          "+f"(acc[mt][nt][2]), "+f"(acc[mt][nt][3])
                        : "r"(a[mt][0]), "r"(a[mt][1]), "r"(a[mt][2]), "r"(a[mt][3]),
                          "r"(b[nt][0]), "r"(b[nt][1]));
                }
        }
    }
    // epilogue: store C (+ optional att dots)
#pragma unroll
    for (int mt = 0; mt < 2; mt++) {
#pragma unroll
        for (int h = 0; h < 2; h++) {
            int row = row0 + wm * 32 + mt * 16 + h * 8 + gp;
            bool ok = (row < NN);
            float ps = 0.f, pd = 0.f;
#pragma unroll
            for (int nt = 0; nt < 8; nt++) {
                int col = wn * 64 + nt * 8 + 2 * qi;
                float c0 = acc[mt][nt][2 * h], c1 = acc[mt][nt][2 * h + 1];
                if (ok) *(float2*)&g_tmp[row * 128 + col] = make_float2(c0, c1);
                if (ATT) {
                    ps = fmaf(c0, s_as[col], fmaf(c1, s_as[col + 1], ps));
                    pd = fmaf(c0, s_ad[col], fmaf(c1, s_ad[col + 1], pd));
                }
            }
            if (ATT) {
                ps += __shfl_xor_sync(0xffffffffu, ps, 1);
                ps += __shfl_xor_sync(0xffffffffu, ps, 2);
                pd += __shfl_xor_sync(0xffffffffu, pd, 1);
                pd += __shfl_xor_sync(0xffffffffu, pd, 2);
                if (qi == 0 && ok) {
                    atomicAdd(&g_als[row], ps);
                    atomicAdd(&g_ald[row], pd);
                }
            }
        }
    }
}

// ---------------- GCN segment aggregation + fused BN stats ----------------
template<bool ZATT>
__global__ void k_gcn_seg(const float* __restrict__ bias) {
    __shared__ float ss[8][128];
    __shared__ float sq[8][128];
    int w = threadIdx.x >> 5, l = threadIdx.x & 31;
    int d = blockIdx.x * 8 + w;
    float4 acc = make_float4(0.f, 0.f, 0.f, 0.f);
    if (d < NN) {
        float dd = g_dis[d];
        float4 b4 = ((const float4*)bias)[l];
        float4 self = ((const float4*)&g_tmp[d * HH])[l];
        float dd2 = dd * dd;
        acc = make_float4(fmaf(self.x, dd2, b4.x), fmaf(self.y, dd2, b4.y),
                          fmaf(self.z, dd2, b4.z), fmaf(self.w, dd2, b4.w));
        int s0 = g_start[d], s1 = g_start[d + 1];
#pragma unroll 4
        for (int j = s0; j < s1; j++) {
            int s = g_esrc[j];
            float nrm = g_dis[s] * dd;
            float4 v = ((const float4*)&g_tmp[s * HH])[l];
            acc.x = fmaf(v.x, nrm, acc.x); acc.y = fmaf(v.y, nrm, acc.y);
            acc.z = fmaf(v.z, nrm, acc.z); acc.w = fmaf(v.w, nrm, acc.w);
        }
        ((float4*)&g_acc[d * HH])[l] = acc;
        if (ZATT && l == 0) { g_als[d] = 0.f; g_ald[d] = 0.f; }
    }
    *(float4*)&ss[w][l * 4] = acc;
    *(float4*)&sq[w][l * 4] = make_float4(acc.x * acc.x, acc.y * acc.y,
                                          acc.z * acc.z, acc.w * acc.w);
    __syncthreads();
    if (threadIdx.x < 128) {
        int c = threadIdx.x;
        float S = 0.f, Q = 0.f;
#pragma unroll
        for (int ww = 0; ww < 8; ww++) { S += ss[ww][c]; Q += sq[ww][c]; }
        int stripe = (blockIdx.x & (NSTRIPE - 1)) * 128 + c;
        atomicAdd(&g_pS[stripe], S);
        atomicAdd(&g_pQ[stripe], Q);
    }
}

// ---------------- GAT softmax + aggregation + fused BN stats ----------------
__global__ void k_gat_seg(const float* __restrict__ bias) {
    __shared__ float ss[8][128];
    __shared__ float sq[8][128];
    int w = threadIdx.x >> 5, l = threadIdx.x & 31;
    int d = blockIdx.x * 8 + w;
    float4 acc = make_float4(0.f, 0.f, 0.f, 0.f);
    if (d < NN) {
        float ald_d = g_ald[d];
        float self_e = lrelu(g_als[d] + ald_d);
        int s0 = g_start[d], s1 = g_start[d + 1];
        float m = self_e;
        for (int j = s0 + l; j < s1; j += 32)
            m = fmaxf(m, lrelu(g_als[g_esrc[j]] + ald_d));
#pragma unroll
        for (int o = 16; o; o >>= 1) m = fmaxf(m, __shfl_xor_sync(0xffffffffu, m, o));
        float den = 0.f;
        for (int j = s0 + l; j < s1; j += 32)
            den += expf(lrelu(g_als[g_esrc[j]] + ald_d) - m);
#pragma unroll
        for (int o = 16; o; o >>= 1) den += __shfl_xor_sync(0xffffffffu, den, o);
        den += expf(self_e - m);
        float rden = 1.0f / den;
        float4 b4 = ((const float4*)bias)[l];
        float a_self = expf(self_e - m) * rden;
        float4 self = ((const float4*)&g_tmp[d * HH])[l];
        acc = make_float4(fmaf(self.x, a_self, b4.x), fmaf(self.y, a_self, b4.y),
                          fmaf(self.z, a_self, b4.z), fmaf(self.w, a_self, b4.w));
#pragma unroll 2
        for (int j = s0; j < s1; j++) {
            int s = g_esrc[j];
            float al = expf(lrelu(g_als[s] + ald_d) - m) * rden;
            float4 v = ((const float4*)&g_tmp[s * HH])[l];
            acc.x = fmaf(v.x, al, acc.x); acc.y = fmaf(v.y, al, acc.y);
            acc.z = fmaf(v.z, al, acc.z); acc.w = fmaf(v.w, al, acc.w);
        }
        ((float4*)&g_acc[d * HH])[l] = acc;
    }
    *(float4*)&ss[w][l * 4] = acc;
    *(float4*)&sq[w][l * 4] = make_float4(acc.x * acc.x, acc.y * acc.y,
                                          acc.z * acc.z, acc.w * acc.w);
    __syncthreads();
    if (threadIdx.x < 128) {
        int c = threadIdx.x;
        float S = 0.f, Q = 0.f;
#pragma unroll
        for (int ww = 0; ww < 8; ww++) { S += ss[ww][c]; Q += sq[ww][c]; }
        int stripe = (blockIdx.x & (NSTRIPE - 1)) * 128 + c;
        atomicAdd(&g_pS[stripe], S);
        atomicAdd(&g_pQ[stripe], Q);
    }
}

// ---------------- BN finalize (reads stripes, re-zeros them) ----------------
__global__ void k_bn_prep(const float* __restrict__ gamma, const float* __restrict__ beta) {
    int c = threadIdx.x;               // 128 threads
    double S = 0.0, Q = 0.0;
    for (int s = 0; s < NSTRIPE; s++) {
        S += (double)g_pS[s * 128 + c];
        Q += (double)g_pQ[s * 128 + c];
        g_pS[s * 128 + c] = 0.f;
        g_pQ[s * 128 + c] = 0.f;
    }
    double mu = S / (double)NN;
    double var = Q / (double)NN - mu * mu;
    float vf = (float)var; if (vf < 0.f) vf = 0.f;
    float sc = gamma[c] * rsqrtf(vf + EPSF);
    g_scale[c] = sc;
    g_shift[c] = beta[c] - (float)mu * sc;
}

// ---------------- pooling (BN3+ReLU fused) + MLP ----------------
__global__ void k_pool_scatter(const int* __restrict__ batch) {
    int w = (blockIdx.x * blockDim.x + threadIdx.x) >> 5;
    if (w >= NN) return;
    int l = threadIdx.x & 31;
    int b = batch[w];
    if (!l) atomicAdd(&g_cnt[b], 1.0f);
    float4 v = ((const float4*)&g_acc[w * HH])[l];
    float4 sc = ((const float4*)g_scale)[l];
    float4 sh = ((const float4*)g_shift)[l];
    v.x = fmaxf(fmaf(v.x, sc.x, sh.x), 0.f);
    v.y = fmaxf(fmaf(v.y, sc.y, sh.y), 0.f);
    v.z = fmaxf(fmaf(v.z, sc.z, sh.z), 0.f);
    v.w = fmaxf(fmaf(v.w, sc.w, sh.w), 0.f);
    red_add_f4(&g_pooled[b * HH + l * 4], v);
}
__global__ void k_mlp1(const float* __restrict__ fw1, const float* __restrict__ fb1) {
    __shared__ float p[HH];
    int g = blockIdx.x, t = threadIdx.x;
    float inv = 1.0f / fmaxf(g_cnt[g], 1.0f);
    p[t] = g_pooled[g * HH + t] * inv;
    __syncthreads();
    float s = fb1[t];
#pragma unroll 8
    for (int k = 0; k < HH; k++) s = fmaf(p[k], fw1[k * HH + t], s);
    g_z[g * HH + t] = fmaxf(s, 0.f);
}
__global__ void k_mlp2(const float* __restrict__ fw2, const float* __restrict__ fb2,
                       float* __restrict__ out) {
    int w = (blockIdx.x * blockDim.x + threadIdx.x) >> 5;
    if (w >= GG) return;
    int l = threadIdx.x & 31;
    float4 z = ((const float4*)&g_z[w * HH])[l];
    float4 ww = ((const float4*)fw2)[l];
    float s = z.x * ww.x + z.y * ww.y + z.z * ww.z + z.w * ww.w;
#pragma unroll
    for (int o = 16; o; o >>= 1) s += __shfl_xor_sync(0xffffffffu, s, o);
    if (!l) out[w] = s + fb2[0];
}

// ---------------- launch ----------------
extern "C" void kernel_launch(void* const* d_in, const int* in_sizes, int n_in,
                              void* d_out, int out_size) {
    const float* x       = (const float*)d_in[0];
    const int*   ei      = (const int*)d_in[1];
    const int*   batch   = (const int*)d_in[2];
    const float* W1      = (const float*)d_in[3];
    const float* b1      = (const float*)d_in[4];
    const float* g1      = (const float*)d_in[5];
    const float* be1     = (const float*)d_in[6];
    const float* Wg      = (const float*)d_in[7];
    const float* att_src = (const float*)d_in[8];
    const float* att_dst = (const float*)d_in[9];
    const float* bg      = (const float*)d_in[10];
    const float* g2      = (const float*)d_in[11];
    const float* be2     = (const float*)d_in[12];
    const float* W3      = (const float*)d_in[13];
    const float* b3      = (const float*)d_in[14];
    const float* g3      = (const float*)d_in[15];
    const float* be3     = (const float*)d_in[16];
    const float* fw1     = (const float*)d_in[17];
    const float* fb1     = (const float*)d_in[18];
    const float* fw2     = (const float*)d_in[19];
    const float* fb2     = (const float*)d_in[20];
    float* out = (float*)d_out;

    const int* src = ei;
    const int* dst = ei + EE;

    const int NB   = (NN + 255) / 256;
    const int EB   = (EE + 255) / 256;
    const int NWB  = (NN * 32 + 255) / 256;
    const int SEGB = (NN + 7) / 8;
    const int GEMB = (NN + 127) / 128;

    // CSR build
    k_zero<<<NB, 256>>>();
    k_hist<<<EB, 256>>>(dst);
    k_scan<<<NCH, 256>>>();
    k_fill<<<EB, 256>>>(src, dst);

    // ---- layer 1: GCN ----
    k_gemm<false, false><<<GEMB, 256>>>(x, W1, nullptr, nullptr);
    k_gcn_seg<true><<<SEGB, 256>>>(b1);           // also zeroes g_als/g_ald
    k_bn_prep<<<1, 128>>>(g1, be1);

    // ---- layer 2: GAT (BN1+ReLU fused into GEMM; att dots in epilogue) ----
    k_gemm<true, true><<<GEMB, 256>>>(nullptr, Wg, att_src, att_dst);
    k_gat_seg<<<SEGB, 256>>>(bg);
    k_bn_prep<<<1, 128>>>(g2, be2);

    // ---- layer 3: GCN (BN2+ReLU fused into GEMM) ----
    k_gemm<true, false><<<GEMB, 256>>>(nullptr, W3, nullptr, nullptr);
    k_gcn_seg<false><<<SEGB, 256>>>(b3);
    k_bn_prep<<<1, 128>>>(g3, be3);

    // ---- pool (BN3+ReLU fused) + MLP ----
    k_pool_scatter<<<NWB, 256>>>(batch);
    k_mlp1<<<GG, 128>>>(fw1, fb1);
    k_mlp2<<<(GG * 32 + 255) / 256, 256>>>(fw2, fb2, out);
}